// round 3
// baseline (speedup 1.0000x reference)
#include <cuda_runtime.h>

// Shape (fixed): main (32,256,56,56) f32, dup (32,64,56,56) f32,
// min/max (256,), vidx (64,) i32, out (32,256,56,56) f32.
// lo <= 0 < hi by construction, inputs finite -> nan_to_num is a no-op
// for the final result (NaN/inf fail the range predicates either way).
#define BB 32
#define CC 256
#define HWSZ (56 * 56)     // 3136
#define HW4 (HWSZ / 4)     // 784 = 3*256 + 16

__device__ __forceinline__ float edac_elem(float m, float d, float lo, float hi) {
    bool mv = (m >= lo) && (m <= hi);
    bool dv = (d >= lo) && (d <= hi);
    // mv&&dv -> min(m,d)  (m==d case: min == m, same as reference)
    // dv&&!mv -> d ; mv&&!dv -> m ; else 0
    if (mv && dv) return fminf(m, d);
    if (dv) return d;
    return mv ? m : 0.0f;
}

__device__ __forceinline__ float clamp_elem(float m, float lo, float hi) {
    return ((m >= lo) && (m <= hi)) ? m : 0.0f;
}

__device__ __forceinline__ float4 edac4(float4 m, float4 d, float lo, float hi) {
    float4 r;
    r.x = edac_elem(m.x, d.x, lo, hi);
    r.y = edac_elem(m.y, d.y, lo, hi);
    r.z = edac_elem(m.z, d.z, lo, hi);
    r.w = edac_elem(m.w, d.w, lo, hi);
    return r;
}

__device__ __forceinline__ float4 clamp4(float4 m, float lo, float hi) {
    float4 r;
    r.x = clamp_elem(m.x, lo, hi);
    r.y = clamp_elem(m.y, lo, hi);
    r.z = clamp_elem(m.z, lo, hi);
    r.w = clamp_elem(m.w, lo, hi);
    return r;
}

// One block per (b,c) plane. grid = B*C = 8192, block = 256.
// No smem, no __syncthreads: each warp finds j via ballot over vidx.
__global__ void __launch_bounds__(256, 8) edac_fused_kernel(
    const float4* __restrict__ main4,
    const float4* __restrict__ dup4,
    const float* __restrict__ min_vals,
    const float* __restrict__ max_vals,
    const int* __restrict__ vidx,
    float4* __restrict__ out4,
    int K)
{
    const int plane = blockIdx.x;
    const int c = plane & (CC - 1);
    const int b = plane >> 8;
    const int t = threadIdx.x;
    const int lane = t & 31;

    // Find j: index into vulnerable_idx with vidx[j] == c (last match wins,
    // mirroring .at[].set semantics for duplicate indices). K is small (64).
    int j = -1;
    for (int base = 0; base < K; base += 32) {
        int v = (base + lane < K) ? __ldg(vidx + base + lane) : (c ^ 1);
        unsigned msk = __ballot_sync(0xffffffffu, v == c);
        if (msk) j = base + 31 - __clz(msk);
    }

    const float lo = __ldg(min_vals + c);
    const float hi = __ldg(max_vals + c);

    const long mbase = (long)plane * HW4;
    const bool tail = (t < HW4 - 3 * 256);   // t < 16

    if (j >= 0) {
        const long dbase = ((long)(b * K + j)) * HW4;
        // Stage 1: chunks 0,1 (16 data regs live)
        {
            float4 m0 = __ldg(main4 + mbase + t);
            float4 m1 = __ldg(main4 + mbase + t + 256);
            float4 d0 = __ldg(dup4 + dbase + t);
            float4 d1 = __ldg(dup4 + dbase + t + 256);
            out4[mbase + t]       = edac4(m0, d0, lo, hi);
            out4[mbase + t + 256] = edac4(m1, d1, lo, hi);
        }
        // Stage 2: chunks 2,3(tail)
        {
            float4 m2 = __ldg(main4 + mbase + t + 512);
            float4 d2 = __ldg(dup4 + dbase + t + 512);
            float4 m3, d3;
            if (tail) {
                m3 = __ldg(main4 + mbase + t + 768);
                d3 = __ldg(dup4 + dbase + t + 768);
            }
            out4[mbase + t + 512] = edac4(m2, d2, lo, hi);
            if (tail) out4[mbase + t + 768] = edac4(m3, d3, lo, hi);
        }
    } else {
        float4 m0 = __ldg(main4 + mbase + t);
        float4 m1 = __ldg(main4 + mbase + t + 256);
        float4 m2 = __ldg(main4 + mbase + t + 512);
        float4 m3;
        if (tail) m3 = __ldg(main4 + mbase + t + 768);
        out4[mbase + t]       = clamp4(m0, lo, hi);
        out4[mbase + t + 256] = clamp4(m1, lo, hi);
        out4[mbase + t + 512] = clamp4(m2, lo, hi);
        if (tail) out4[mbase + t + 768] = clamp4(m3, lo, hi);
    }
}

extern "C" void kernel_launch(void* const* d_in, const int* in_sizes, int n_in,
                              void* d_out, int out_size) {
    const float* main_out = (const float*)d_in[0];
    const float* dup_out  = (const float*)d_in[1];
    const float* min_vals = (const float*)d_in[2];
    const float* max_vals = (const float*)d_in[3];
    const int*   vidx     = (const int*)d_in[4];
    float* out = (float*)d_out;

    int K = in_sizes[4];

    edac_fused_kernel<<<BB * CC, 256>>>(
        (const float4*)main_out, (const float4*)dup_out,
        min_vals, max_vals, vidx, (float4*)out, K);
}

// round 4
// speedup vs baseline: 1.0561x; 1.0561x over previous
#include <cuda_runtime.h>

// Shape (fixed): main (32,256,56,56) f32, dup (32,64,56,56) f32,
// min/max (256,), vidx (64,) i32, out (32,256,56,56) f32.
// lo <= 0 < hi by construction, inputs finite -> nan_to_num is a no-op
// for the final result (NaN/inf fail the range predicates either way).
#define BB 32
#define CC 256
#define HWSZ (56 * 56)     // 3136
#define HW4 (HWSZ / 4)     // 784 = 3*256 + 16

__device__ __forceinline__ float edac_elem(float m, float d, float lo, float hi) {
    bool mv = (m >= lo) && (m <= hi);
    bool dv = (d >= lo) && (d <= hi);
    if (mv && dv) return fminf(m, d);   // m==d case: fminf == m, same as ref
    if (dv) return d;
    return mv ? m : 0.0f;
}

__device__ __forceinline__ float clamp_elem(float m, float lo, float hi) {
    return ((m >= lo) && (m <= hi)) ? m : 0.0f;
}

__device__ __forceinline__ float4 edac4(float4 m, float4 d, float lo, float hi) {
    float4 r;
    r.x = edac_elem(m.x, d.x, lo, hi);
    r.y = edac_elem(m.y, d.y, lo, hi);
    r.z = edac_elem(m.z, d.z, lo, hi);
    r.w = edac_elem(m.w, d.w, lo, hi);
    return r;
}

__device__ __forceinline__ float4 clamp4(float4 m, float lo, float hi) {
    float4 r;
    r.x = clamp_elem(m.x, lo, hi);
    r.y = clamp_elem(m.y, lo, hi);
    r.z = clamp_elem(m.z, lo, hi);
    r.w = clamp_elem(m.w, lo, hi);
    return r;
}

// One block per (b,c) plane. grid = B*C = 8192, block = 256.
// Each thread: float4 indices t, t+256, t+512, (t+768 if t<16).
// All loads front-batched (MLP_p1 = 8 on the vulnerable path), streaming
// cache hints (pure pass-through traffic, no reuse).
__global__ void __launch_bounds__(256) edac_fused_kernel(
    const float4* __restrict__ main4,
    const float4* __restrict__ dup4,
    const float* __restrict__ min_vals,
    const float* __restrict__ max_vals,
    const int* __restrict__ vidx,
    float4* __restrict__ out4,
    int K)
{
    const int plane = blockIdx.x;
    const int c = plane & (CC - 1);
    const int b = plane >> 8;
    const int t = threadIdx.x;
    const int lane = t & 31;

    // j = last index with vidx[j] == c (mirrors .at[].set on duplicates).
    int j = -1;
    for (int base = 0; base < K; base += 32) {
        int v = (base + lane < K) ? __ldg(vidx + base + lane) : (c ^ 1);
        unsigned msk = __ballot_sync(0xffffffffu, v == c);
        if (msk) j = base + 31 - __clz(msk);
    }

    const float lo = __ldg(min_vals + c);
    const float hi = __ldg(max_vals + c);

    const int mbase = plane * HW4;                  // < 2^23, int ok
    const bool tail = (t < HW4 - 3 * 256);          // t < 16

    // Front-batch main loads.
    float4 m0 = __ldcs(main4 + mbase + t);
    float4 m1 = __ldcs(main4 + mbase + t + 256);
    float4 m2 = __ldcs(main4 + mbase + t + 512);
    float4 m3;
    if (tail) m3 = __ldcs(main4 + mbase + t + 768);

    if (j >= 0) {
        const int dbase = (b * K + j) * HW4;        // < 2^21, int ok
        float4 d0 = __ldcs(dup4 + dbase + t);
        float4 d1 = __ldcs(dup4 + dbase + t + 256);
        float4 d2 = __ldcs(dup4 + dbase + t + 512);
        float4 d3;
        if (tail) d3 = __ldcs(dup4 + dbase + t + 768);

        __stcs(out4 + mbase + t,       edac4(m0, d0, lo, hi));
        __stcs(out4 + mbase + t + 256, edac4(m1, d1, lo, hi));
        __stcs(out4 + mbase + t + 512, edac4(m2, d2, lo, hi));
        if (tail) __stcs(out4 + mbase + t + 768, edac4(m3, d3, lo, hi));
    } else {
        __stcs(out4 + mbase + t,       clamp4(m0, lo, hi));
        __stcs(out4 + mbase + t + 256, clamp4(m1, lo, hi));
        __stcs(out4 + mbase + t + 512, clamp4(m2, lo, hi));
        if (tail) __stcs(out4 + mbase + t + 768, clamp4(m3, lo, hi));
    }
}

extern "C" void kernel_launch(void* const* d_in, const int* in_sizes, int n_in,
                              void* d_out, int out_size) {
    const float* main_out = (const float*)d_in[0];
    const float* dup_out  = (const float*)d_in[1];
    const float* min_vals = (const float*)d_in[2];
    const float* max_vals = (const float*)d_in[3];
    const int*   vidx     = (const int*)d_in[4];
    float* out = (float*)d_out;

    int K = in_sizes[4];

    edac_fused_kernel<<<BB * CC, 256>>>(
        (const float4*)main_out, (const float4*)dup_out,
        min_vals, max_vals, vidx, (float4*)out, K);
}